// round 4
// baseline (speedup 1.0000x reference)
#include <cuda_runtime.h>

// ---------------------------------------------------------------------------
// MPNN: h = relu(x@We+be); per branch:
//   m[n] = sum_k relu( g[idx] + phi(dist) )      (g = h@Wm_top, phi = rbf@Wm_bot + bm)
//   out  = sigmoid( a[n] + m[n]@Wu_bot )          (a = h@Wu_top + bu)
// ---------------------------------------------------------------------------

#define NF        12
#define BN        16
#define NN        4096
#define KK        32
#define E_TBL     704          // phi table entries over [0, 0.3]
#define C_CHUNKS  6
#define CSZ       683          // ceil(4096/6)
#define THREADS_MAIN 512

// Scratch (device globals: allocation-free rule)
__device__ float g_buf[3][BN][NN][NF];     // h @ Wm_top          (9.4 MB)
__device__ float a_buf[3][BN][NN][NF];     // h @ Wu_top + bu     (9.4 MB)
__device__ float tbl_buf[3][E_TBL][NF];    // phi(dist) table incl. bm

struct WPtrs {
    const float* We; const float* be;
    const float* Wm[3]; const float* bm[3];
    const float* Wu[3]; const float* bu[3];
    const float* d[3];
};

// ---------------------------------------------------------------------------
// Kernel 0: build phi tables.  phi[br][e][f] = bm[f] + sum_j exp(-(x_e-c_j)^2/(2s^2)) * Wm_bot[j][f]
// ---------------------------------------------------------------------------
__global__ void build_table_kernel(WPtrs w) {
    int id = blockIdx.x * blockDim.x + threadIdx.x;
    if (id >= 3 * E_TBL * NF) return;
    int f  = id % NF;
    int e  = (id / NF) % E_TBL;
    int br = id / (NF * E_TBL);
    float xe = (float)e * (0.3f / (float)(E_TBL - 1));
    const float inv2s2 = 1.0f / (2.0f * 0.015f * 0.015f);
    float s = w.bm[br][f];
    #pragma unroll
    for (int j = 0; j < 12; j++) {
        float c = 0.3f * (float)j / 11.0f;
        float t = xe - c;
        s += __expf(-t * t * inv2s2) * w.Wm[br][(12 + j) * NF + f];
    }
    tbl_buf[br][e][f] = s;
}

// ---------------------------------------------------------------------------
// Kernel 1: per-node precompute: h, then g (3 branches) and a (3 branches).
// ---------------------------------------------------------------------------
__global__ void precompute_kernel(WPtrs w, const float* __restrict__ x) {
    __shared__ float We_s[4 * NF];
    __shared__ float be_s[NF];
    __shared__ float Wm_s[3][NF * NF];   // top 12 rows of Wm
    __shared__ float Wu_s[3][NF * NF];   // top 12 rows of Wu
    __shared__ float bu_s[3][NF];

    int tid = threadIdx.x;
    if (tid < 48) We_s[tid] = w.We[tid];
    if (tid < NF) be_s[tid] = w.be[tid];
    #pragma unroll
    for (int br = 0; br < 3; br++) {
        for (int i = tid; i < NF * NF; i += blockDim.x) {
            Wm_s[br][i] = w.Wm[br][i];   // rows 0..11 are the first 144 elems
            Wu_s[br][i] = w.Wu[br][i];
        }
        if (tid < NF) bu_s[br][tid] = w.bu[br][tid];
    }
    __syncthreads();

    int node = blockIdx.x * blockDim.x + tid;      // grid sized exactly BN*NN
    int b = node / NN, n = node % NN;

    float4 xv = ((const float4*)x)[node];
    float xr[4] = {xv.x, xv.y, xv.z, xv.w};

    float h[NF];
    #pragma unroll
    for (int c = 0; c < NF; c++) {
        float s = be_s[c];
        #pragma unroll
        for (int i = 0; i < 4; i++) s = fmaf(xr[i], We_s[i * NF + c], s);
        h[c] = fmaxf(s, 0.0f);
    }

    #pragma unroll
    for (int br = 0; br < 3; br++) {
        float g[NF], a[NF];
        #pragma unroll
        for (int f = 0; f < NF; f++) {
            float sg = 0.0f;
            float sa = bu_s[br][f];
            #pragma unroll
            for (int c = 0; c < NF; c++) {
                sg = fmaf(h[c], Wm_s[br][c * NF + f], sg);
                sa = fmaf(h[c], Wu_s[br][c * NF + f], sa);
            }
            g[f] = sg; a[f] = sa;
        }
        float4* gp = (float4*)&g_buf[br][b][n][0];
        gp[0] = make_float4(g[0], g[1], g[2], g[3]);
        gp[1] = make_float4(g[4], g[5], g[6], g[7]);
        gp[2] = make_float4(g[8], g[9], g[10], g[11]);
        float4* ap = (float4*)&a_buf[br][b][n][0];
        ap[0] = make_float4(a[0], a[1], a[2], a[3]);
        ap[1] = make_float4(a[4], a[5], a[6], a[7]);
        ap[2] = make_float4(a[8], a[9], a[10], a[11]);
    }
}

// ---------------------------------------------------------------------------
// Kernel 2: main edge loop. One block = (batch, branch, node-chunk).
// smem: g for all 4096 nodes (192KB) + phi table (33KB) + Wu_bot (576B).
// ---------------------------------------------------------------------------
#define SMEM_FLOATS (NN * NF + E_TBL * NF + NF * NF)
#define SMEM_BYTES  (SMEM_FLOATS * 4)

__global__ void __launch_bounds__(THREADS_MAIN, 1)
main_kernel(WPtrs w, float* __restrict__ out) {
    extern __shared__ float sm[];
    float* g_s  = sm;                       // NN*NF
    float* t_s  = sm + NN * NF;             // E_TBL*NF
    float* wu_s = t_s + E_TBL * NF;         // 144 (Wu rows 12..23)

    int bid   = blockIdx.x;
    int chunk = bid % C_CHUNKS;
    int pair  = bid / C_CHUNKS;
    int br    = pair % 3;
    int b     = pair / 3;
    int tid   = threadIdx.x;

    // cooperative smem fill (coalesced float4)
    {
        const float4* gsrc = (const float4*)&g_buf[br][b][0][0];
        float4* gdst = (float4*)g_s;
        #pragma unroll 4
        for (int i = tid; i < NN * NF / 4; i += THREADS_MAIN) gdst[i] = gsrc[i];
        const float4* tsrc = (const float4*)&tbl_buf[br][0][0];
        float4* tdst = (float4*)t_s;
        for (int i = tid; i < E_TBL * NF / 4; i += THREADS_MAIN) tdst[i] = tsrc[i];
        if (tid < NF * NF) wu_s[tid] = w.Wu[br][NF * NF + tid];  // bottom rows
    }
    __syncthreads();

    int n0 = chunk * CSZ;
    int n1 = n0 + CSZ; if (n1 > NN) n1 = NN;

    const float scale = (float)(E_TBL - 1) / 0.3f;
    const float2* dbase = (const float2*)w.d[br] + (size_t)b * NN * KK;

    for (int n = n0 + tid; n < n1; n += THREADS_MAIN) {
        const float2* dp = dbase + (size_t)n * KK;

        float m[NF];
        #pragma unroll
        for (int f = 0; f < NF; f++) m[f] = 0.0f;

        #pragma unroll 4
        for (int k = 0; k < KK; k++) {
            float2 e = __ldg(&dp[k]);
            int   j  = (int)e.x;
            float t  = e.y * scale;
            int   ti = (int)t;
            if (ti > E_TBL - 2) ti = E_TBL - 2;
            float fr = t - (float)ti;
            const float4* tp = (const float4*)(t_s + ti * NF);
            const float4* gp = (const float4*)(g_s + j * NF);
            #pragma unroll
            for (int q = 0; q < 3; q++) {
                float4 lo = tp[q];
                float4 hi = tp[q + 3];
                float4 gg = gp[q];
                float v;
                v = fmaf(fr, hi.x - lo.x, lo.x) + gg.x; m[4*q+0] += fmaxf(v, 0.0f);
                v = fmaf(fr, hi.y - lo.y, lo.y) + gg.y; m[4*q+1] += fmaxf(v, 0.0f);
                v = fmaf(fr, hi.z - lo.z, lo.z) + gg.z; m[4*q+2] += fmaxf(v, 0.0f);
                v = fmaf(fr, hi.w - lo.w, lo.w) + gg.w; m[4*q+3] += fmaxf(v, 0.0f);
            }
        }

        // epilogue: z = a + m @ Wu_bot ; out = sigmoid(z)
        float z[NF];
        {
            const float4* ap = (const float4*)&a_buf[br][b][n][0];
            float4 a0 = ap[0], a1 = ap[1], a2 = ap[2];
            z[0]=a0.x; z[1]=a0.y; z[2]=a0.z;  z[3]=a0.w;
            z[4]=a1.x; z[5]=a1.y; z[6]=a1.z;  z[7]=a1.w;
            z[8]=a2.x; z[9]=a2.y; z[10]=a2.z; z[11]=a2.w;
        }
        #pragma unroll
        for (int i = 0; i < NF; i++) {
            float mi = m[i];
            #pragma unroll
            for (int f = 0; f < NF; f++) z[f] = fmaf(mi, wu_s[i * NF + f], z[f]);
        }
        float o[NF];
        #pragma unroll
        for (int f = 0; f < NF; f++) o[f] = 1.0f / (1.0f + __expf(-z[f]));

        float4* op = (float4*)(out + (((size_t)br * BN + b) * NN + n) * NF);
        op[0] = make_float4(o[0], o[1], o[2],  o[3]);
        op[1] = make_float4(o[4], o[5], o[6],  o[7]);
        op[2] = make_float4(o[8], o[9], o[10], o[11]);
    }
}

// ---------------------------------------------------------------------------
// launch
// ---------------------------------------------------------------------------
extern "C" void kernel_launch(void* const* d_in, const int* in_sizes, int n_in,
                              void* d_out, int out_size) {
    (void)in_sizes; (void)n_in; (void)out_size;

    WPtrs w;
    const float* x = (const float*)d_in[0];
    w.d[0]  = (const float*)d_in[1];    // d1
    w.d[1]  = (const float*)d_in[2];    // d0
    w.d[2]  = (const float*)d_in[3];    // dm1
    // d_in[4] = mask (unused by the reference math)
    w.We    = (const float*)d_in[5];
    w.be    = (const float*)d_in[6];
    w.Wm[0] = (const float*)d_in[7];   w.bm[0] = (const float*)d_in[8];
    w.Wu[0] = (const float*)d_in[9];   w.bu[0] = (const float*)d_in[10];
    w.Wm[1] = (const float*)d_in[11];  w.bm[1] = (const float*)d_in[12];
    w.Wu[1] = (const float*)d_in[13];  w.bu[1] = (const float*)d_in[14];
    w.Wm[2] = (const float*)d_in[15];  w.bm[2] = (const float*)d_in[16];
    w.Wu[2] = (const float*)d_in[17];  w.bu[2] = (const float*)d_in[18];

    cudaFuncSetAttribute(main_kernel,
                         cudaFuncAttributeMaxDynamicSharedMemorySize, SMEM_BYTES);

    int tbl_threads = 3 * E_TBL * NF;
    build_table_kernel<<<(tbl_threads + 255) / 256, 256>>>(w);
    precompute_kernel<<<(BN * NN) / 256, 256>>>(w, x);
    main_kernel<<<BN * 3 * C_CHUNKS, THREADS_MAIN, SMEM_BYTES>>>(w, (float*)d_out);
}

// round 5
// speedup vs baseline: 1.5182x; 1.5182x over previous
#include <cuda_runtime.h>
#include <cuda_fp16.h>

// ---------------------------------------------------------------------------
// MPNN: h = relu(x@We+be); per branch:
//   m[n] = sum_k relu( g[idx] + phi(dist) )    (g = h@Wm_top, phi = rbf@Wm_bot + bm)
//   out  = sigmoid( a[n] + m[n]@Wu_bot )        (a = h@Wu_top + bu)
// g and phi-table quantized to fp16 in smem; fp32 accumulation.
// Main kernel: warp covers 2 nodes (16 lanes x 2 edges each), butterfly reduce.
// ---------------------------------------------------------------------------

#define NF        12
#define BN        16
#define NN        4096
#define KK        32
#define N_ENT     703            // interp intervals over [0,0.3]
#define TBL_BLOCKS 99            // ceil(3*703*12 / 256)
#define PRE_BLOCKS 256           // BN*NN/256
#define C_CHUNKS  3
#define CSZ       1366           // chunk sizes 1366,1366,1364 (all even)
#define TMAIN     1024

// device-global scratch (allocation-free rule)
__device__ __half g_half[3][BN][NN][NF];          // 4.7 MB
__device__ float  a_buf [3][BN][NN][NF];          // 9.4 MB
__device__ __half tbl_half[3][N_ENT][2 * NF];     // lo[12], slope[12] per entry

struct WPtrs {
    const float* We; const float* be;
    const float* Wm[3]; const float* bm[3];
    const float* Wu[3]; const float* bu[3];
    const float* d[3];
};

static __device__ __forceinline__ __half2 u2h2(unsigned u) {
    __half2 h; *reinterpret_cast<unsigned*>(&h) = u; return h;
}
static __device__ __forceinline__ unsigned h2u2(__half2 h) {
    return *reinterpret_cast<unsigned*>(&h);
}

// ---------------------------------------------------------------------------
// Fused prep kernel: blocks [0,TBL_BLOCKS) build the fp16 phi tables,
// blocks [TBL_BLOCKS, TBL_BLOCKS+PRE_BLOCKS) do per-node precompute of g, a.
// ---------------------------------------------------------------------------
__global__ void prep_kernel(WPtrs w, const float* __restrict__ x) {
    __shared__ float We_s[4 * NF];
    __shared__ float be_s[NF];
    __shared__ float Wm_s[3][NF * NF];
    __shared__ float Wu_s[3][NF * NF];
    __shared__ float bu_s[3][NF];

    int tid = threadIdx.x;
    int bid = blockIdx.x;

    if (bid < TBL_BLOCKS) {
        int id = bid * 256 + tid;
        if (id < 3 * N_ENT * NF) {
            int f  = id % NF;
            int e  = (id / NF) % N_ENT;
            int br = id / (NF * N_ENT);
            const float H = 0.3f / (float)N_ENT;
            const float inv2s2 = 1.0f / (2.0f * 0.015f * 0.015f);
            float x0 = (float)e * H;
            float x1 = x0 + H;
            float p0 = w.bm[br][f], p1 = p0;
            #pragma unroll
            for (int j = 0; j < 12; j++) {
                float c  = 0.3f * (float)j / 11.0f;
                float wt = w.Wm[br][(12 + j) * NF + f];
                float t0 = x0 - c, t1 = x1 - c;
                p0 += __expf(-t0 * t0 * inv2s2) * wt;
                p1 += __expf(-t1 * t1 * inv2s2) * wt;
            }
            tbl_half[br][e][f]      = __float2half_rn(p0);
            tbl_half[br][e][NF + f] = __float2half_rn(p1 - p0);
        }
        return;
    }

    // ---- precompute role ----
    if (tid < 48) We_s[tid] = w.We[tid];
    if (tid < NF) be_s[tid] = w.be[tid];
    #pragma unroll
    for (int br = 0; br < 3; br++) {
        for (int i = tid; i < NF * NF; i += 256) {
            Wm_s[br][i] = w.Wm[br][i];     // rows 0..11 of Wm
            Wu_s[br][i] = w.Wu[br][i];     // rows 0..11 of Wu
        }
        if (tid < NF) bu_s[br][tid] = w.bu[br][tid];
    }
    __syncthreads();

    int node = (bid - TBL_BLOCKS) * 256 + tid;   // 0 .. BN*NN-1
    int b = node / NN, n = node % NN;

    float4 xv = ((const float4*)x)[node];
    float xr[4] = {xv.x, xv.y, xv.z, xv.w};

    float h[NF];
    #pragma unroll
    for (int c = 0; c < NF; c++) {
        float s = be_s[c];
        #pragma unroll
        for (int i = 0; i < 4; i++) s = fmaf(xr[i], We_s[i * NF + c], s);
        h[c] = fmaxf(s, 0.0f);
    }

    #pragma unroll
    for (int br = 0; br < 3; br++) {
        float g[NF], a[NF];
        #pragma unroll
        for (int f = 0; f < NF; f++) {
            float sg = 0.0f;
            float sa = bu_s[br][f];
            #pragma unroll
            for (int c = 0; c < NF; c++) {
                sg = fmaf(h[c], Wm_s[br][c * NF + f], sg);
                sa = fmaf(h[c], Wu_s[br][c * NF + f], sa);
            }
            g[f] = sg; a[f] = sa;
        }
        // g -> fp16 (24B)
        uint2* gp = (uint2*)&g_half[br][b][n][0];
        gp[0] = make_uint2(h2u2(__floats2half2_rn(g[0], g[1])),
                           h2u2(__floats2half2_rn(g[2], g[3])));
        gp[1] = make_uint2(h2u2(__floats2half2_rn(g[4], g[5])),
                           h2u2(__floats2half2_rn(g[6], g[7])));
        gp[2] = make_uint2(h2u2(__floats2half2_rn(g[8], g[9])),
                           h2u2(__floats2half2_rn(g[10], g[11])));
        float4* ap = (float4*)&a_buf[br][b][n][0];
        ap[0] = make_float4(a[0], a[1], a[2],  a[3]);
        ap[1] = make_float4(a[4], a[5], a[6],  a[7]);
        ap[2] = make_float4(a[8], a[9], a[10], a[11]);
    }
}

// ---------------------------------------------------------------------------
// Main kernel
// ---------------------------------------------------------------------------
#define SMEM_G_BYTES (NN * NF * 2)            // 98304
#define SMEM_T_BYTES (N_ENT * 2 * NF * 2)     // 33744
#define SMEM_BYTES   (SMEM_G_BYTES + SMEM_T_BYTES + NF * NF * 4)

__device__ __forceinline__ void edge_accum(
    const unsigned char* sm_base, float idxf, float dist, float scale, float* m)
{
    int j = (int)idxf;
    float t = dist * scale;
    int ti = (int)t;
    ti = (ti > N_ENT - 1) ? (N_ENT - 1) : ti;
    float fr = t - (float)ti;
    __half2 fr2 = __float2half2_rn(fr);

    const uint4* tp = (const uint4*)(sm_base + SMEM_G_BYTES + ti * 48);
    uint4 T0 = tp[0], T1 = tp[1], T2 = tp[2];
    const uint2* gp = (const uint2*)(sm_base + j * 24);
    uint2 G0 = gp[0], G1 = gp[1], G2 = gp[2];

    unsigned loW[6] = {T0.x, T0.y, T0.z, T0.w, T1.x, T1.y};
    unsigned slW[6] = {T1.z, T1.w, T2.x, T2.y, T2.z, T2.w};
    unsigned gW [6] = {G0.x, G0.y, G1.x, G1.y, G2.x, G2.y};

    const __half2 zero2 = __float2half2_rn(0.0f);
    #pragma unroll
    for (int q = 0; q < 6; q++) {
        __half2 v = __hfma2(fr2, u2h2(slW[q]), __hadd2(u2h2(loW[q]), u2h2(gW[q])));
        v = __hmax2(v, zero2);
        float2 vf = __half22float2(v);
        m[2 * q]     += vf.x;
        m[2 * q + 1] += vf.y;
    }
}

__global__ void __launch_bounds__(TMAIN, 1)
main_kernel(WPtrs w, float* __restrict__ out) {
    extern __shared__ unsigned char sm[];
    float* wu_s = (float*)(sm + SMEM_G_BYTES + SMEM_T_BYTES);

    int bid   = blockIdx.x;
    int chunk = bid % C_CHUNKS;
    int pair  = bid / C_CHUNKS;
    int br    = pair % 3;
    int b     = pair / 3;
    int tid   = threadIdx.x;

    // cooperative smem fills (uint4, fully coalesced)
    {
        const uint4* gsrc = (const uint4*)&g_half[br][b][0][0];
        uint4* gdst = (uint4*)sm;
        #pragma unroll 2
        for (int i = tid; i < SMEM_G_BYTES / 16; i += TMAIN) gdst[i] = gsrc[i];
        const uint4* tsrc = (const uint4*)&tbl_half[br][0][0];
        uint4* tdst = (uint4*)(sm + SMEM_G_BYTES);
        for (int i = tid; i < SMEM_T_BYTES / 16; i += TMAIN) tdst[i] = tsrc[i];
        if (tid < NF * NF) wu_s[tid] = w.Wu[br][NF * NF + tid];   // Wu rows 12..23
    }
    __syncthreads();

    int n0 = chunk * CSZ;
    int n1 = n0 + CSZ; if (n1 > NN) n1 = NN;
    int cnt = n1 - n0;                        // even for all chunks

    int lane = tid & 31;
    int warp = tid >> 5;
    int sub  = lane >> 4;                     // 0/1: which of the warp's 2 nodes
    int l    = lane & 15;                     // edge-pair index within node

    const float scale = (float)N_ENT / 0.3f;
    const float4* dvec = (const float4*)w.d[br] + (size_t)b * NN * (KK / 2);
    const float*  abase = &a_buf[br][b][0][0];
    float* obase = out + (size_t)(br * BN + b) * NN * NF;

    for (int p = warp; 2 * p < cnt; p += 32) {
        int n = n0 + 2 * p + sub;

        float m[NF];
        #pragma unroll
        for (int f = 0; f < NF; f++) m[f] = 0.0f;

        // one fully coalesced 16B load: 2 edges (idx0,dist0,idx1,dist1)
        float4 e4 = __ldg(&dvec[(size_t)n * (KK / 2) + l]);
        edge_accum(sm, e4.x, e4.y, scale, m);
        edge_accum(sm, e4.z, e4.w, scale, m);

        // butterfly sum within each 16-lane group (leaves full sum on all lanes)
        #pragma unroll
        for (int off = 8; off >= 1; off >>= 1) {
            #pragma unroll
            for (int f = 0; f < NF; f++)
                m[f] += __shfl_xor_sync(0xffffffffu, m[f], off);
        }

        int el = lane - (sub << 4);           // 0..15 within group
        if (el < NF) {
            float z = __ldg(&abase[n * NF + el]);
            #pragma unroll
            for (int i = 0; i < NF; i++)
                z = fmaf(m[i], wu_s[i * NF + el], z);
            obase[n * NF + el] = 1.0f / (1.0f + __expf(-z));
        }
    }
}

// ---------------------------------------------------------------------------
// launch
// ---------------------------------------------------------------------------
extern "C" void kernel_launch(void* const* d_in, const int* in_sizes, int n_in,
                              void* d_out, int out_size) {
    (void)in_sizes; (void)n_in; (void)out_size;

    WPtrs w;
    const float* x = (const float*)d_in[0];
    w.d[0]  = (const float*)d_in[1];    // d1
    w.d[1]  = (const float*)d_in[2];    // d0
    w.d[2]  = (const float*)d_in[3];    // dm1
    // d_in[4] = mask (all ones; unused)
    w.We    = (const float*)d_in[5];
    w.be    = (const float*)d_in[6];
    w.Wm[0] = (const float*)d_in[7];   w.bm[0] = (const float*)d_in[8];
    w.Wu[0] = (const float*)d_in[9];   w.bu[0] = (const float*)d_in[10];
    w.Wm[1] = (const float*)d_in[11];  w.bm[1] = (const float*)d_in[12];
    w.Wu[1] = (const float*)d_in[13];  w.bu[1] = (const float*)d_in[14];
    w.Wm[2] = (const float*)d_in[15];  w.bm[2] = (const float*)d_in[16];
    w.Wu[2] = (const float*)d_in[17];  w.bu[2] = (const float*)d_in[18];

    cudaFuncSetAttribute(main_kernel,
                         cudaFuncAttributeMaxDynamicSharedMemorySize, SMEM_BYTES);

    prep_kernel<<<TBL_BLOCKS + PRE_BLOCKS, 256>>>(w, x);
    main_kernel<<<BN * 3 * C_CHUNKS, TMAIN, SMEM_BYTES>>>(w, (float*)d_out);
}

// round 7
// speedup vs baseline: 1.5993x; 1.0534x over previous
#include <cuda_runtime.h>
#include <cuda_fp16.h>

// ---------------------------------------------------------------------------
// MPNN: h = relu(x@We+be); per branch:
//   m[n] = sum_k relu( g[idx] + phi(dist) )    (g = h@Wm_top, phi = rbf@Wm_bot + bm)
//   out  = sigmoid( a[n] + m[n]@Wu_bot )        (a = h@Wu_top + bu)
// fp16 smem tables, fp32 accumulation. Warp = 2 nodes (16 lanes x 2 edges).
// g split into 16B+8B arrays (bank-uniform); table 256 entries, quad-interleaved.
// 2 blocks x 768 threads per SM.
// ---------------------------------------------------------------------------

#define NF        12
#define BN        16
#define NN        4096
#define KK        32
#define N_ENT     256
#define TBL_BLOCKS 9             // ceil(3*256*3 / 256)
#define PRE_BLOCKS 256           // BN*NN/256
#define C_CHUNKS  6
#define CSZ       684            // chunks: 684*5 + 676, all even
#define TMAIN     768
#define NWARPS    (TMAIN / 32)

// device-global scratch (allocation-free rule)
__device__ uint4  gA_buf[3][BN][NN];          // fp16 g features 0..7   (3 MB)
__device__ uint2  gB_buf[3][BN][NN];          // fp16 g features 8..11  (1.5 MB)
__device__ float  a_buf [3][BN][NN][NF];      // fp32 (9.4 MB)
__device__ uint4  tbl_buf[3][N_ENT][3];       // quad q: {lo(4 fp16), slope(4 fp16)}

struct WPtrs {
    const float* We; const float* be;
    const float* Wm[3]; const float* bm[3];
    const float* Wu[3]; const float* bu[3];
    const float* d[3];
};

static __device__ __forceinline__ __half2 u2h2(unsigned u) {
    __half2 h; *reinterpret_cast<unsigned*>(&h) = u; return h;
}
static __device__ __forceinline__ unsigned pack2(float a, float b) {
    __half2 h = __floats2half2_rn(a, b);
    return *reinterpret_cast<unsigned*>(&h);
}

// ---------------------------------------------------------------------------
// Fused prep: blocks [0,TBL_BLOCKS) build phi tables; rest do per-node g/a.
// ---------------------------------------------------------------------------
__global__ void prep_kernel(WPtrs w, const float* __restrict__ x) {
    __shared__ float We_s[4 * NF];
    __shared__ float be_s[NF];
    __shared__ float Wm_s[3][NF * NF];
    __shared__ float Wu_s[3][NF * NF];
    __shared__ float bu_s[3][NF];

    int tid = threadIdx.x;
    int bid = blockIdx.x;

    if (bid < TBL_BLOCKS) {
        int id = bid * 256 + tid;
        if (id < 3 * N_ENT * 3) {
            int q  = id % 3;
            int e  = (id / 3) % N_ENT;
            int br = id / (3 * N_ENT);
            const float H = 0.3f / (float)N_ENT;
            const float inv2s2 = 1.0f / (2.0f * 0.015f * 0.015f);
            float x0 = (float)e * H, x1 = x0 + H;
            float p0[4], sl[4];
            #pragma unroll
            for (int t = 0; t < 4; t++) {
                int f = q * 4 + t;
                float a0 = w.bm[br][f], a1 = a0;
                #pragma unroll
                for (int j = 0; j < 12; j++) {
                    float c  = 0.3f * (float)j / 11.0f;
                    float wt = w.Wm[br][(12 + j) * NF + f];
                    float t0 = x0 - c, t1 = x1 - c;
                    a0 += __expf(-t0 * t0 * inv2s2) * wt;
                    a1 += __expf(-t1 * t1 * inv2s2) * wt;
                }
                p0[t] = a0; sl[t] = a1 - a0;
            }
            tbl_buf[br][e][q] = make_uint4(pack2(p0[0], p0[1]), pack2(p0[2], p0[3]),
                                           pack2(sl[0], sl[1]), pack2(sl[2], sl[3]));
        }
        return;
    }

    // ---- per-node precompute ----
    if (tid < 48) We_s[tid] = w.We[tid];
    if (tid < NF) be_s[tid] = w.be[tid];
    #pragma unroll
    for (int br = 0; br < 3; br++) {
        for (int i = tid; i < NF * NF; i += 256) {
            Wm_s[br][i] = w.Wm[br][i];     // rows 0..11 of Wm
            Wu_s[br][i] = w.Wu[br][i];     // rows 0..11 of Wu
        }
        if (tid < NF) bu_s[br][tid] = w.bu[br][tid];
    }
    __syncthreads();

    int node = (bid - TBL_BLOCKS) * 256 + tid;   // 0 .. BN*NN-1
    int b = node / NN, n = node % NN;

    float4 xv = ((const float4*)x)[node];
    float xr[4] = {xv.x, xv.y, xv.z, xv.w};

    float h[NF];
    #pragma unroll
    for (int c = 0; c < NF; c++) {
        float s = be_s[c];
        #pragma unroll
        for (int i = 0; i < 4; i++) s = fmaf(xr[i], We_s[i * NF + c], s);
        h[c] = fmaxf(s, 0.0f);
    }

    #pragma unroll
    for (int br = 0; br < 3; br++) {
        float g[NF], a[NF];
        #pragma unroll
        for (int f = 0; f < NF; f++) {
            float sg = 0.0f;
            float sa = bu_s[br][f];
            #pragma unroll
            for (int c = 0; c < NF; c++) {
                sg = fmaf(h[c], Wm_s[br][c * NF + f], sg);
                sa = fmaf(h[c], Wu_s[br][c * NF + f], sa);
            }
            g[f] = sg; a[f] = sa;
        }
        gA_buf[br][b][n] = make_uint4(pack2(g[0], g[1]), pack2(g[2], g[3]),
                                      pack2(g[4], g[5]), pack2(g[6], g[7]));
        gB_buf[br][b][n] = make_uint2(pack2(g[8], g[9]), pack2(g[10], g[11]));
        float4* ap = (float4*)&a_buf[br][b][n][0];
        ap[0] = make_float4(a[0], a[1], a[2],  a[3]);
        ap[1] = make_float4(a[4], a[5], a[6],  a[7]);
        ap[2] = make_float4(a[8], a[9], a[10], a[11]);
    }
}

// ---------------------------------------------------------------------------
// Main kernel
// ---------------------------------------------------------------------------
#define SMEM_A_OFF   0
#define SMEM_B_OFF   (NN * 16)                      // 65536
#define SMEM_T_OFF   (SMEM_B_OFF + NN * 8)          // 98304
#define SMEM_W_OFF   (SMEM_T_OFF + N_ENT * 48)      // 110592
#define SMEM_BYTES   (SMEM_W_OFF + NF * NF * 4)     // 111168

__device__ __forceinline__ void edge_accum(
    const uint4* __restrict__ sA, const uint2* __restrict__ sB,
    const uint4* __restrict__ sT, float idxf, float dist, float scale, float* m)
{
    int j = (int)idxf;
    float t = dist * scale;
    int ti = (int)t;
    ti = (ti > N_ENT - 1) ? (N_ENT - 1) : ti;
    __half2 fr2 = __float2half2_rn(t - (float)ti);
    const __half2 z2 = __float2half2_rn(0.0f);

    uint4 G0 = sA[j];
    uint2 G1 = sB[j];
    const uint4* tp = sT + ti * 3;

    uint4 T = tp[0];
    { __half2 v = __hmax2(__hfma2(fr2, u2h2(T.z), __hadd2(u2h2(T.x), u2h2(G0.x))), z2);
      float2 f = __half22float2(v); m[0] += f.x; m[1] += f.y; }
    { __half2 v = __hmax2(__hfma2(fr2, u2h2(T.w), __hadd2(u2h2(T.y), u2h2(G0.y))), z2);
      float2 f = __half22float2(v); m[2] += f.x; m[3] += f.y; }
    T = tp[1];
    { __half2 v = __hmax2(__hfma2(fr2, u2h2(T.z), __hadd2(u2h2(T.x), u2h2(G0.z))), z2);
      float2 f = __half22float2(v); m[4] += f.x; m[5] += f.y; }
    { __half2 v = __hmax2(__hfma2(fr2, u2h2(T.w), __hadd2(u2h2(T.y), u2h2(G0.w))), z2);
      float2 f = __half22float2(v); m[6] += f.x; m[7] += f.y; }
    T = tp[2];
    { __half2 v = __hmax2(__hfma2(fr2, u2h2(T.z), __hadd2(u2h2(T.x), u2h2(G1.x))), z2);
      float2 f = __half22float2(v); m[8] += f.x; m[9] += f.y; }
    { __half2 v = __hmax2(__hfma2(fr2, u2h2(T.w), __hadd2(u2h2(T.y), u2h2(G1.y))), z2);
      float2 f = __half22float2(v); m[10] += f.x; m[11] += f.y; }
}

__global__ void __launch_bounds__(TMAIN, 2)
main_kernel(WPtrs w, float* __restrict__ out) {
    extern __shared__ unsigned char sm[];
    const uint4* sA = (const uint4*)(sm + SMEM_A_OFF);
    const uint2* sB = (const uint2*)(sm + SMEM_B_OFF);
    const uint4* sT = (const uint4*)(sm + SMEM_T_OFF);
    float*       wu = (float*)(sm + SMEM_W_OFF);

    int bid   = blockIdx.x;
    int chunk = bid % C_CHUNKS;
    int pair  = bid / C_CHUNKS;
    int br    = pair % 3;
    int b     = pair / 3;
    int tid   = threadIdx.x;

    // cooperative smem fills (coalesced)
    {
        const uint4* s0 = &gA_buf[br][b][0];
        uint4* d0 = (uint4*)(sm + SMEM_A_OFF);
        #pragma unroll 2
        for (int i = tid; i < NN; i += TMAIN) d0[i] = s0[i];
        const uint2* s1 = &gB_buf[br][b][0];
        uint2* d1 = (uint2*)(sm + SMEM_B_OFF);
        for (int i = tid; i < NN; i += TMAIN) d1[i] = s1[i];
        const uint4* s2 = &tbl_buf[br][0][0];
        uint4* d2 = (uint4*)(sm + SMEM_T_OFF);
        for (int i = tid; i < N_ENT * 3; i += TMAIN) d2[i] = s2[i];
        if (tid < NF * NF) wu[tid] = w.Wu[br][NF * NF + tid];   // Wu rows 12..23
    }
    __syncthreads();

    int n0 = chunk * CSZ;
    int n1 = n0 + CSZ; if (n1 > NN) n1 = NN;
    int cnt = n1 - n0;                        // even for all chunks

    int lane = tid & 31;
    int warp = tid >> 5;
    int sub  = lane >> 4;                     // which of the warp's 2 nodes
    int l    = lane & 15;                     // edge-pair index within node

    const float scale = (float)N_ENT / 0.3f;
    const float4* dvec = (const float4*)w.d[br] + (size_t)b * NN * (KK / 2);
    const float*  abase = &a_buf[br][b][0][0];
    float* obase = out + (size_t)(br * BN + b) * NN * NF;

    for (int p = warp; 2 * p < cnt; p += NWARPS) {
        int n = n0 + 2 * p + sub;

        float m[NF];
        #pragma unroll
        for (int f = 0; f < NF; f++) m[f] = 0.0f;

        // one coalesced 16B load: 2 edges (idx0,dist0,idx1,dist1)
        float4 e4 = __ldg(&dvec[(size_t)n * (KK / 2) + l]);
        edge_accum(sA, sB, sT, e4.x, e4.y, scale, m);
        edge_accum(sA, sB, sT, e4.z, e4.w, scale, m);

        // butterfly sum within each 16-lane group
        #pragma unroll
        for (int off = 8; off >= 1; off >>= 1) {
            #pragma unroll
            for (int f = 0; f < NF; f++)
                m[f] += __shfl_xor_sync(0xffffffffu, m[f], off);
        }

        int el = lane - (sub << 4);           // 0..15 within group
        if (el < NF) {
            float z = __ldg(&abase[n * NF + el]);
            #pragma unroll
            for (int i = 0; i < NF; i++)
                z = fmaf(m[i], wu[i * NF + el], z);
            obase[n * NF + el] = __fdividef(1.0f, 1.0f + __expf(-z));
        }
    }
}

// ---------------------------------------------------------------------------
// launch
// ---------------------------------------------------------------------------
extern "C" void kernel_launch(void* const* d_in, const int* in_sizes, int n_in,
                              void* d_out, int out_size) {
    (void)in_sizes; (void)n_in; (void)out_size;

    WPtrs w;
    const float* x = (const float*)d_in[0];
    w.d[0]  = (const float*)d_in[1];    // d1
    w.d[1]  = (const float*)d_in[2];    // d0
    w.d[2]  = (const float*)d_in[3];    // dm1
    // d_in[4] = mask (all ones; unused)
    w.We    = (const float*)d_in[5];
    w.be    = (const float*)d_in[6];
    w.Wm[0] = (const float*)d_in[7];   w.bm[0] = (const float*)d_in[8];
    w.Wu[0] = (const float*)d_in[9];   w.bu[0] = (const float*)d_in[10];
    w.Wm[1] = (const float*)d_in[11];  w.bm[1] = (const float*)d_in[12];
    w.Wu[1] = (const float*)d_in[13];  w.bu[1] = (const float*)d_in[14];
    w.Wm[2] = (const float*)d_in[15];  w.bm[2] = (const float*)d_in[16];
    w.Wu[2] = (const float*)d_in[17];  w.bu[2] = (const float*)d_in[18];

    cudaFuncSetAttribute(main_kernel,
                         cudaFuncAttributeMaxDynamicSharedMemorySize, SMEM_BYTES);

    prep_kernel<<<TBL_BLOCKS + PRE_BLOCKS, 256>>>(w, x);
    main_kernel<<<BN * 3 * C_CHUNKS, TMAIN, SMEM_BYTES>>>(w, (float*)d_out);
}

// round 9
// speedup vs baseline: 1.8445x; 1.1534x over previous
#include <cuda_runtime.h>
#include <cuda_fp16.h>

// ---------------------------------------------------------------------------
// MPNN: h = relu(x@We+be); per branch:
//   m[n] = sum_k relu( g[idx] + phi(dist) )    (g = h@Wm_top, phi = rbf@Wm_bot + bm)
//   out  = sigmoid( a[n] + m[n]@Wu_bot )        (a = h@Wu_top + bu)
// fp16 smem tables, fp32 accumulation. Warp = 4 nodes (8 lanes x 4 edges),
// 3-round butterfly. Transposed Wu_bot rows for vector epilogue loads.
// ---------------------------------------------------------------------------

#define NF        12
#define BN        16
#define NN        4096
#define KK        32
#define N_ENT     256
#define TBL_BLOCKS 9             // ceil(3*256*3 / 256)
#define PRE_BLOCKS 256           // BN*NN/256
#define C_CHUNKS  6
#define CSZ       684            // chunks: 684*5 + 676, all divisible by 4
#define TMAIN     768
#define NWARPS    (TMAIN / 32)

// device-global scratch (allocation-free rule)
__device__ uint4  gA_buf[3][BN][NN];          // fp16 g features 0..7   (3 MB)
__device__ uint2  gB_buf[3][BN][NN];          // fp16 g features 8..11  (1.5 MB)
__device__ float  a_buf [3][BN][NN][NF];      // fp32 (9.4 MB)
__device__ uint4  tbl_buf[3][N_ENT][3];       // quad q: {lo(4 fp16), slope(4 fp16)}

struct WPtrs {
    const float* We; const float* be;
    const float* Wm[3]; const float* bm[3];
    const float* Wu[3]; const float* bu[3];
    const float* d[3];
};

static __device__ __forceinline__ __half2 u2h2(unsigned u) {
    __half2 h; *reinterpret_cast<unsigned*>(&h) = u; return h;
}
static __device__ __forceinline__ unsigned pack2(float a, float b) {
    __half2 h = __floats2half2_rn(a, b);
    return *reinterpret_cast<unsigned*>(&h);
}

// ---------------------------------------------------------------------------
// Fused prep: blocks [0,TBL_BLOCKS) build phi tables; rest do per-node g/a.
// ---------------------------------------------------------------------------
__global__ void prep_kernel(WPtrs w, const float* __restrict__ x) {
    __shared__ float We_s[4 * NF];
    __shared__ float be_s[NF];
    __shared__ float Wm_s[3][NF * NF];
    __shared__ float Wu_s[3][NF * NF];
    __shared__ float bu_s[3][NF];

    int tid = threadIdx.x;
    int bid = blockIdx.x;

    if (bid < TBL_BLOCKS) {
        int id = bid * 256 + tid;
        if (id < 3 * N_ENT * 3) {
            int q  = id % 3;
            int e  = (id / 3) % N_ENT;
            int br = id / (3 * N_ENT);
            const float H = 0.3f / (float)N_ENT;
            const float inv2s2 = 1.0f / (2.0f * 0.015f * 0.015f);
            float x0 = (float)e * H, x1 = x0 + H;
            float p0[4], sl[4];
            #pragma unroll
            for (int t = 0; t < 4; t++) {
                int f = q * 4 + t;
                float a0 = w.bm[br][f], a1 = a0;
                #pragma unroll
                for (int j = 0; j < 12; j++) {
                    float c  = 0.3f * (float)j / 11.0f;
                    float wt = w.Wm[br][(12 + j) * NF + f];
                    float t0 = x0 - c, t1 = x1 - c;
                    a0 += __expf(-t0 * t0 * inv2s2) * wt;
                    a1 += __expf(-t1 * t1 * inv2s2) * wt;
                }
                p0[t] = a0; sl[t] = a1 - a0;
            }
            tbl_buf[br][e][q] = make_uint4(pack2(p0[0], p0[1]), pack2(p0[2], p0[3]),
                                           pack2(sl[0], sl[1]), pack2(sl[2], sl[3]));
        }
        return;
    }

    // ---- per-node precompute ----
    if (tid < 48) We_s[tid] = w.We[tid];
    if (tid < NF) be_s[tid] = w.be[tid];
    #pragma unroll
    for (int br = 0; br < 3; br++) {
        for (int i = tid; i < NF * NF; i += 256) {
            Wm_s[br][i] = w.Wm[br][i];     // rows 0..11 of Wm
            Wu_s[br][i] = w.Wu[br][i];     // rows 0..11 of Wu
        }
        if (tid < NF) bu_s[br][tid] = w.bu[br][tid];
    }
    __syncthreads();

    int node = (bid - TBL_BLOCKS) * 256 + tid;   // 0 .. BN*NN-1
    int b = node / NN, n = node % NN;

    float4 xv = ((const float4*)x)[node];
    float xr[4] = {xv.x, xv.y, xv.z, xv.w};

    float h[NF];
    #pragma unroll
    for (int c = 0; c < NF; c++) {
        float s = be_s[c];
        #pragma unroll
        for (int i = 0; i < 4; i++) s = fmaf(xr[i], We_s[i * NF + c], s);
        h[c] = fmaxf(s, 0.0f);
    }

    #pragma unroll
    for (int br = 0; br < 3; br++) {
        float g[NF], a[NF];
        #pragma unroll
        for (int f = 0; f < NF; f++) {
            float sg = 0.0f;
            float sa = bu_s[br][f];
            #pragma unroll
            for (int c = 0; c < NF; c++) {
                sg = fmaf(h[c], Wm_s[br][c * NF + f], sg);
                sa = fmaf(h[c], Wu_s[br][c * NF + f], sa);
            }
            g[f] = sg; a[f] = sa;
        }
        gA_buf[br][b][n] = make_uint4(pack2(g[0], g[1]), pack2(g[2], g[3]),
                                      pack2(g[4], g[5]), pack2(g[6], g[7]));
        gB_buf[br][b][n] = make_uint2(pack2(g[8], g[9]), pack2(g[10], g[11]));
        float4* ap = (float4*)&a_buf[br][b][n][0];
        ap[0] = make_float4(a[0], a[1], a[2],  a[3]);
        ap[1] = make_float4(a[4], a[5], a[6],  a[7]);
        ap[2] = make_float4(a[8], a[9], a[10], a[11]);
    }
}

// ---------------------------------------------------------------------------
// Main kernel
// ---------------------------------------------------------------------------
#define SMEM_A_OFF   0
#define SMEM_B_OFF   (NN * 16)                      // 65536
#define SMEM_T_OFF   (SMEM_B_OFF + NN * 8)          // 98304
#define SMEM_W_OFF   (SMEM_T_OFF + N_ENT * 48)      // 110592
#define SMEM_BYTES   (SMEM_W_OFF + NF * NF * 4)     // 111168

__device__ __forceinline__ void edge_accum(
    const uint4* __restrict__ sA, const uint2* __restrict__ sB,
    const uint4* __restrict__ sT, float idxf, float dist, float scale, float* m)
{
    int j = (int)idxf;
    float t = dist * scale;
    int ti = (int)t;
    ti = (ti > N_ENT - 1) ? (N_ENT - 1) : ti;
    __half2 fr2 = __float2half2_rn(t - (float)ti);
    const __half2 z2 = __float2half2_rn(0.0f);

    uint4 G0 = sA[j];
    uint2 G1 = sB[j];
    const uint4* tp = sT + ti * 3;

    uint4 T = tp[0];
    { __half2 v = __hmax2(__hfma2(fr2, u2h2(T.z), __hadd2(u2h2(T.x), u2h2(G0.x))), z2);
      float2 f = __half22float2(v); m[0] += f.x; m[1] += f.y; }
    { __half2 v = __hmax2(__hfma2(fr2, u2h2(T.w), __hadd2(u2h2(T.y), u2h2(G0.y))), z2);
      float2 f = __half22float2(v); m[2] += f.x; m[3] += f.y; }
    T = tp[1];
    { __half2 v = __hmax2(__hfma2(fr2, u2h2(T.z), __hadd2(u2h2(T.x), u2h2(G0.z))), z2);
      float2 f = __half22float2(v); m[4] += f.x; m[5] += f.y; }
    { __half2 v = __hmax2(__hfma2(fr2, u2h2(T.w), __hadd2(u2h2(T.y), u2h2(G0.w))), z2);
      float2 f = __half22float2(v); m[6] += f.x; m[7] += f.y; }
    T = tp[2];
    { __half2 v = __hmax2(__hfma2(fr2, u2h2(T.z), __hadd2(u2h2(T.x), u2h2(G1.x))), z2);
      float2 f = __half22float2(v); m[8] += f.x; m[9] += f.y; }
    { __half2 v = __hmax2(__hfma2(fr2, u2h2(T.w), __hadd2(u2h2(T.y), u2h2(G1.y))), z2);
      float2 f = __half22float2(v); m[10] += f.x; m[11] += f.y; }
}

__global__ void __launch_bounds__(TMAIN, 2)
main_kernel(WPtrs w, float* __restrict__ out) {
    extern __shared__ unsigned char sm[];
    const uint4* sA = (const uint4*)(sm + SMEM_A_OFF);
    const uint2* sB = (const uint2*)(sm + SMEM_B_OFF);
    const uint4* sT = (const uint4*)(sm + SMEM_T_OFF);
    float*       wuT = (float*)(sm + SMEM_W_OFF);    // wuT[f][i] = Wu[(12+i)*12+f]

    int bid   = blockIdx.x;
    int chunk = bid % C_CHUNKS;
    int pair  = bid / C_CHUNKS;
    int br    = pair % 3;
    int b     = pair / 3;
    int tid   = threadIdx.x;

    // cooperative smem fills (coalesced)
    {
        const uint4* s0 = &gA_buf[br][b][0];
        uint4* d0 = (uint4*)(sm + SMEM_A_OFF);
        #pragma unroll 2
        for (int i = tid; i < NN; i += TMAIN) d0[i] = s0[i];
        const uint2* s1 = &gB_buf[br][b][0];
        uint2* d1 = (uint2*)(sm + SMEM_B_OFF);
        for (int i = tid; i < NN; i += TMAIN) d1[i] = s1[i];
        const uint4* s2 = &tbl_buf[br][0][0];
        uint4* d2 = (uint4*)(sm + SMEM_T_OFF);
        for (int i = tid; i < N_ENT * 3; i += TMAIN) d2[i] = s2[i];
        if (tid < NF * NF) {
            int i = tid / NF, f = tid % NF;          // transpose bottom Wu rows
            wuT[f * NF + i] = w.Wu[br][NF * NF + i * NF + f];
        }
    }
    __syncthreads();

    int n0 = chunk * CSZ;
    int n1 = n0 + CSZ; if (n1 > NN) n1 = NN;
    int quads = (n1 - n0) >> 2;               // chunk sizes divisible by 4

    int lane = tid & 31;
    int warp = tid >> 5;
    int sub  = lane >> 3;                     // node within the warp's quad (0..3)
    int l    = lane & 7;                      // lane within node group

    const float scale = (float)N_ENT / 0.3f;
    const float4* dvec = (const float4*)w.d[br] + (size_t)b * NN * (KK / 2);
    const float*  abase = &a_buf[br][b][0][0];
    float* obase = out + (size_t)(br * BN + b) * NN * NF;

    for (int q = warp; q < quads; q += NWARPS) {
        int n = n0 + 4 * q + sub;

        // two coalesced 16B loads: 4 edges per lane
        const float4* ep = &dvec[(size_t)n * (KK / 2)];
        float4 eA = __ldg(&ep[l]);
        float4 eB = __ldg(&ep[l + 8]);

        float m[NF];
        #pragma unroll
        for (int f = 0; f < NF; f++) m[f] = 0.0f;

        edge_accum(sA, sB, sT, eA.x, eA.y, scale, m);
        edge_accum(sA, sB, sT, eA.z, eA.w, scale, m);
        edge_accum(sA, sB, sT, eB.x, eB.y, scale, m);
        edge_accum(sA, sB, sT, eB.z, eB.w, scale, m);

        // 3-round butterfly within each 8-lane group
        #pragma unroll
        for (int off = 4; off >= 1; off >>= 1) {
            #pragma unroll
            for (int f = 0; f < NF; f++)
                m[f] += __shfl_xor_sync(0xffffffffu, m[f], off);
        }

        // epilogue: feature f1 = l (all lanes), f2 = l+8 (lanes 0..3)
        {
            int f1 = l;
            const float4* rp = (const float4*)(wuT + f1 * NF);
            float4 r0 = rp[0], r1 = rp[1], r2 = rp[2];
            float z = __ldg(&abase[n * NF + f1]);
            z = fmaf(m[0], r0.x, z); z = fmaf(m[1], r0.y, z);
            z = fmaf(m[2], r0.z, z); z = fmaf(m[3], r0.w, z);
            z = fmaf(m[4], r1.x, z); z = fmaf(m[5], r1.y, z);
            z = fmaf(m[6], r1.z, z); z = fmaf(m[7], r1.w, z);
            z = fmaf(m[8], r2.x, z); z = fmaf(m[9], r2.y, z);
            z = fmaf(m[10], r2.z, z); z = fmaf(m[11], r2.w, z);
            obase[n * NF + f1] = __fdividef(1.0f, 1.0f + __expf(-z));
        }
        if (l < 4) {
            int f2 = l + 8;
            const float4* rp = (const float4*)(wuT + f2 * NF);
            float4 r0 = rp[0], r1 = rp[1], r2 = rp[2];
            float z = __ldg(&abase[n * NF + f2]);
            z = fmaf(m[0], r0.x, z); z = fmaf(m[1], r0.y, z);
            z = fmaf(m[2], r0.z, z); z = fmaf(m[3], r0.w, z);
            z = fmaf(m[4], r1.x, z); z = fmaf(m[5], r1.y, z);
            z = fmaf(m[6], r1.z, z); z = fmaf(m[7], r1.w, z);
            z = fmaf(m[8], r2.x, z); z = fmaf(m[9], r2.y, z);
            z = fmaf(m[10], r2.z, z); z = fmaf(m[11], r2.w, z);
            obase[n * NF + f2] = __fdividef(1.0f, 1.0f + __expf(-z));
        }
    }
}

// ---------------------------------------------------------------------------
// launch
// ---------------------------------------------------------------------------
extern "C" void kernel_launch(void* const* d_in, const int* in_sizes, int n_in,
                              void* d_out, int out_size) {
    (void)in_sizes; (void)n_in; (void)out_size;

    WPtrs w;
    const float* x = (const float*)d_in[0];
    w.d[0]  = (const float*)d_in[1];    // d1
    w.d[1]  = (const float*)d_in[2];    // d0
    w.d[2]  = (const float*)d_in[3];    // dm1
    // d_in[4] = mask (all ones; unused)
    w.We    = (const float*)d_in[5];
    w.be    = (const float*)d_in[6];
    w.Wm[0] = (const float*)d_in[7];   w.bm[0] = (const float*)d_in[8];
    w.Wu[0] = (const float*)d_in[9];   w.bu[0] = (const float*)d_in[10];
    w.Wm[1] = (const float*)d_in[11];  w.bm[1] = (const float*)d_in[12];
    w.Wu[1] = (const float*)d_in[13];  w.bu[1] = (const float*)d_in[14];
    w.Wm[2] = (const float*)d_in[15];  w.bm[2] = (const float*)d_in[16];
    w.Wu[2] = (const float*)d_in[17];  w.bu[2] = (const float*)d_in[18];

    cudaFuncSetAttribute(main_kernel,
                         cudaFuncAttributeMaxDynamicSharedMemorySize, SMEM_BYTES);

    prep_kernel<<<TBL_BLOCKS + PRE_BLOCKS, 256>>>(w, x);
    main_kernel<<<BN * 3 * C_CHUNKS, TMAIN, SMEM_BYTES>>>(w, (float*)d_out);
}